// round 5
// baseline (speedup 1.0000x reference)
#include <cuda_runtime.h>
#include <cuda_bf16.h>

// AngleTensor: out[b,i,j,k] = mask * arccos( u_ij . u_ik ),  u_ij = (p_j-p_i)/d_ij
// B=8, N=128 fixed.  grid=(N,B), 128 threads per block (one block per (b,i)).
//
// Thread t owns k = 8*(t&15) .. +7; walks j = (t>>4) step 8 (16 iters).
// Math packed 2-wide with fp32x2 PTX (fma.rn.f32x2 / mul.rn.f32x2, sm_100+).
// No per-element mask: compute everything unmasked (zero-vector rows keep all
// values finite), then after __syncthreads() overwrite row j==i, column k==i,
// and the j==k diagonal with zeros (384 stores vs 33k mask FMULs per block).
// acos via A&S 4.4.45 (abs err 6.7e-5 rad).

#define N_FIXED 128
#define PI_F 3.14159265358979f

typedef unsigned long long u64;

__device__ __forceinline__ u64 pk(float a, float b) {
    u64 d;
    asm("mov.b64 %0, {%1, %2};" : "=l"(d)
        : "r"(__float_as_uint(a)), "r"(__float_as_uint(b)));
    return d;
}
__device__ __forceinline__ void upk(u64 v, float& a, float& b) {
    unsigned lo, hi;
    asm("mov.b64 {%0, %1}, %2;" : "=r"(lo), "=r"(hi) : "l"(v));
    a = __uint_as_float(lo);
    b = __uint_as_float(hi);
}
__device__ __forceinline__ u64 fma2(u64 a, u64 b, u64 c) {
    u64 d;
    asm("fma.rn.f32x2 %0, %1, %2, %3;" : "=l"(d) : "l"(a), "l"(b), "l"(c));
    return d;
}
__device__ __forceinline__ u64 mul2(u64 a, u64 b) {
    u64 d;
    asm("mul.rn.f32x2 %0, %1, %2;" : "=l"(d) : "l"(a), "l"(b));
    return d;
}

#define ABS2 0x7FFFFFFF7FFFFFFFULL

__global__ __launch_bounds__(128) void angle_kernel(
    const float* __restrict__ pos,   // (B, N, 3)
    const float* __restrict__ dist,  // (B, N, N)
    float* __restrict__ out)         // (B, N, N, N)
{
    const int i = blockIdx.x;
    const int b = blockIdx.y;
    const int t = threadIdx.x;
    const int N = N_FIXED;

    __shared__ float4 sh[N_FIXED];   // unit vectors (w unused)

    const float pix = pos[(b * N + i) * 3 + 0];
    const float piy = pos[(b * N + i) * 3 + 1];
    const float piz = pos[(b * N + i) * 3 + 2];

    {
        const int j = t;
        const float px = pos[(b * N + j) * 3 + 0];
        const float py = pos[(b * N + j) * 3 + 1];
        const float pz = pos[(b * N + j) * 3 + 2];
        const float d  = dist[((size_t)b * N + i) * N + j];
        const float inv = (d > 0.0f) ? (1.0f / d) : 0.0f;  // zero vec on j==i
        sh[j] = make_float4((px - pix) * inv, (py - piy) * inv, (pz - piz) * inv, 0.0f);
    }
    __syncthreads();

    const int k0 = (t & 15) * 8;   // owns k0..k0+7
    const int jq = t >> 4;         // j phase 0..7

    // packed uk pairs: (k0,k1)(k2,k3)(k4,k5)(k6,k7) per dimension
    u64 kx[4], ky[4], kz[4];
#pragma unroll
    for (int m = 0; m < 4; m++) {
        const float4 a = sh[k0 + 2 * m + 0];
        const float4 c = sh[k0 + 2 * m + 1];
        kx[m] = pk(a.x, c.x);
        ky[m] = pk(a.y, c.y);
        kz[m] = pk(a.z, c.z);
    }

    // packed polynomial / misc constants (built once, hoisted)
    const u64 C3 = pk(-0.0187293f, -0.0187293f);
    const u64 C2 = pk( 0.0742610f,  0.0742610f);
    const u64 C1 = pk(-0.2121144f, -0.2121144f);
    const u64 C0 = pk( 1.5707288f,  1.5707288f);
    const u64 NEG1 = pk(-1.0f, -1.0f);
    const u64 ONE2 = pk( 1.0f,  1.0f);

    float* orow = out + (((size_t)b * N + i) * N) * N;

#pragma unroll 2
    for (int j = jq; j < N; j += 8) {
        const float4 uj = sh[j];
        const u64 jx = pk(uj.x, uj.x);
        const u64 jy = pk(uj.y, uj.y);
        const u64 jz = pk(uj.z, uj.z);

        u64 cc[4], xx[4], yy[4], pp[4];
#pragma unroll
        for (int m = 0; m < 4; m++) {
            u64 c = mul2(jx, kx[m]);
            c = fma2(jy, ky[m], c);
            c = fma2(jz, kz[m], c);
            cc[m] = c;
            xx[m] = c & ABS2;                 // packed |c|
            yy[m] = fma2(xx[m], NEG1, ONE2);  // packed 1-|c|
            // packed A&S 4.4.45 poly in |c|
            u64 p = fma2(xx[m], C3, C2);
            p = fma2(p, xx[m], C1);
            pp[m] = fma2(p, xx[m], C0);
        }

        float av[8];
#pragma unroll
        for (int m = 0; m < 4; m++) {
            float y0, y1, p0, p1, c0, c1;
            upk(yy[m], y0, y1);
            upk(pp[m], p0, p1);
            upk(cc[m], c0, c1);
            y0 = fmaxf(y0, 1e-12f);           // guard rsqrt (x may round >1)
            y1 = fmaxf(y1, 1e-12f);
            const float s0 = y0 * rsqrtf(y0); // sqrt(y)
            const float s1 = y1 * rsqrtf(y1);
            const float b0 = s0 * p0;
            const float b1 = s1 * p1;
            av[2 * m + 0] = (c0 < 0.0f) ? (PI_F - b0) : b0;
            av[2 * m + 1] = (c1 < 0.0f) ? (PI_F - b1) : b1;
        }

        float* o = orow + (size_t)j * N + k0;
        *reinterpret_cast<float4*>(o + 0) = make_float4(av[0], av[1], av[2], av[3]);
        *reinterpret_cast<float4*>(o + 4) = make_float4(av[4], av[5], av[6], av[7]);
    }

    // fixups: must land after all main-loop stores to these addresses
    __syncthreads();

    // row j == i  (128 floats, 32 threads x float4)
    if (t < 32)
        *reinterpret_cast<float4*>(orow + (size_t)i * N + 4 * t) =
            make_float4(0.0f, 0.0f, 0.0f, 0.0f);
    // column k == i and diagonal j == k (one scalar store each per thread)
    orow[(size_t)t * N + i] = 0.0f;
    orow[(size_t)t * N + t] = 0.0f;
}

extern "C" void kernel_launch(void* const* d_in, const int* in_sizes, int n_in,
                              void* d_out, int out_size) {
    const float* pos  = (const float*)d_in[0];   // positions (B, N, 3)
    const float* dist = (const float*)d_in[1];   // dist_matrix (B, N, N)
    float* out = (float*)d_out;                  // (B, N, N, N) fp32

    const int N = (int)(3LL * in_sizes[1] / in_sizes[0]);   // = 128
    const int B = in_sizes[0] / (3 * N);                    // = 8

    dim3 grid(N, B);
    angle_kernel<<<grid, 128>>>(pos, dist, out);
}

// round 6
// speedup vs baseline: 1.0189x; 1.0189x over previous
#include <cuda_runtime.h>
#include <cuda_bf16.h>

// AngleTensor: out[b,i,j,k] = mask * arccos( u_ij . u_ik ),  u_ij = (p_j-p_i)/d_ij
// B=8, N=128 fixed.  grid=(N,B), 128 threads/block (one block per (b,i)).
//
// Scalar fp32 (R2 execution shape — best measured issue efficiency).
// Thread t owns k = 8*(t&15) .. +7; walks j = (t>>4) step 8 (16 iters).
// Hot loop has NO mask math: masked entries (j==i row, k==i col, j==k diag)
// are overwritten with zeros after a __syncthreads() fixup.
// acos via A&S 4.4.45 rebased in y = 1-|c| so |c| is never materialized:
//   acos(|c|) = sqrt(y) * q(y),  q(y)=1.4141461+0.1197803y+0.0180731y^2+0.0187293y^3
//   c<0 -> pi - that.   (abs err ~6.7e-5 rad)

#define N_FIXED 128
#define PI_F 3.14159265358979f

__global__ __launch_bounds__(128) void angle_kernel(
    const float* __restrict__ pos,   // (B, N, 3)
    const float* __restrict__ dist,  // (B, N, N)
    float* __restrict__ out)         // (B, N, N, N)
{
    const int i = blockIdx.x;
    const int b = blockIdx.y;
    const int t = threadIdx.x;
    const int N = N_FIXED;

    __shared__ float4 sh[N_FIXED];   // unit vectors

    const float pix = pos[(b * N + i) * 3 + 0];
    const float piy = pos[(b * N + i) * 3 + 1];
    const float piz = pos[(b * N + i) * 3 + 2];

    {
        const int j = t;
        const float px = pos[(b * N + j) * 3 + 0];
        const float py = pos[(b * N + j) * 3 + 1];
        const float pz = pos[(b * N + j) * 3 + 2];
        const float d  = dist[((size_t)b * N + i) * N + j];
        const float inv = (d > 0.0f) ? (1.0f / d) : 0.0f;  // zero vec on j==i
        sh[j] = make_float4((px - pix) * inv, (py - piy) * inv, (pz - piz) * inv, 0.0f);
    }
    __syncthreads();

    const int k0 = (t & 15) * 8;   // owns k0..k0+7
    const int jq = t >> 4;         // j phase 0..7

    float kx[8], ky[8], kz[8];
#pragma unroll
    for (int m = 0; m < 8; m++) {
        const float4 u = sh[k0 + m];
        kx[m] = u.x; ky[m] = u.y; kz[m] = u.z;
    }

    float* orow = out + (((size_t)b * N + i) * N) * N;
    float* o = orow + (size_t)jq * N + k0;   // strength-reduced output cursor

#pragma unroll 2
    for (int j = jq; j < N; j += 8) {
        const float4 uj = sh[j];

        float av[8];
#pragma unroll
        for (int m = 0; m < 8; m++) {
            float c = uj.x * kx[m];
            c = fmaf(uj.y, ky[m], c);
            c = fmaf(uj.z, kz[m], c);

            // y = 1 - |c|  (single FADD with |src| modifier); clamp guards
            // rounding |c|>1 and doubles as NaN-safety
            const float y = fmaxf(1.0f - fabsf(c), 1e-12f);
            const float r = rsqrtf(y);
            const float s = y * r;                  // sqrt(y)

            float q = fmaf(y, 0.0187293f, 0.0180731f);
            q = fmaf(q, y, 0.1197803f);
            q = fmaf(q, y, 1.4141461f);

            const float bb = s * q;
            av[m] = (c < 0.0f) ? (PI_F - bb) : bb;
        }

        *reinterpret_cast<float4*>(o + 0) = make_float4(av[0], av[1], av[2], av[3]);
        *reinterpret_cast<float4*>(o + 4) = make_float4(av[4], av[5], av[6], av[7]);
        o += 8 * N_FIXED;
    }

    // fixups: land after all main-loop stores (same block wrote every address)
    __syncthreads();

    // row j == i (128 floats, 32 threads x float4)
    if (t < 32)
        *reinterpret_cast<float4*>(orow + (size_t)i * N + 4 * t) =
            make_float4(0.0f, 0.0f, 0.0f, 0.0f);
    // column k == i and diagonal j == k
    orow[(size_t)t * N + i] = 0.0f;
    orow[(size_t)t * N + t] = 0.0f;
}

extern "C" void kernel_launch(void* const* d_in, const int* in_sizes, int n_in,
                              void* d_out, int out_size) {
    const float* pos  = (const float*)d_in[0];   // positions (B, N, 3)
    const float* dist = (const float*)d_in[1];   // dist_matrix (B, N, N)
    float* out = (float*)d_out;                  // (B, N, N, N) fp32

    const int N = (int)(3LL * in_sizes[1] / in_sizes[0]);   // = 128
    const int B = in_sizes[0] / (3 * N);                    // = 8

    dim3 grid(N, B);
    angle_kernel<<<grid, 128>>>(pos, dist, out);
}

// round 7
// speedup vs baseline: 1.6888x; 1.6575x over previous
#include <cuda_runtime.h>
#include <cuda_bf16.h>

// AngleTensor: out[b,i,j,k] = mask * arccos( u_ij . u_ik ),  u_ij = (p_j-p_i)/d_ij
// B=8, N=128 fixed.  grid=(N,B), 128 threads/block (one block per (b,i)).
//
// EXACT R2 execution shape (best measured: issue 74%, regs 48, perfectly
// coalesced 512B stores): thread t owns k = 4*(t&31)..+3, walks j = (t>>5)
// step 4 (warp-uniform j -> LDS broadcast; 32 lanes x float4 = contiguous STG).
// Changes vs R2 are arithmetic-only:
//  - no mask math in the loop; masked entries (row j==i, col k==i, diag j==k)
//    zeroed by a post-__syncthreads() fixup (384 stores vs 33k FMULs).
//  - acos rebased in y = 1-|c|: acos(|c|) = sqrt(y)*q(y),
//    q(y) = 1.4141461 + 0.1197803 y + 0.0180731 y^2 + 0.0187293 y^3
//    (A&S 4.4.45 with x = 1-y; abs err ~6.7e-5 rad); c<0 -> pi - value.

#define N_FIXED 128
#define PI_F 3.14159265358979f

__global__ __launch_bounds__(128) void angle_kernel(
    const float* __restrict__ pos,   // (B, N, 3)
    const float* __restrict__ dist,  // (B, N, N)
    float* __restrict__ out)         // (B, N, N, N)
{
    const int i = blockIdx.x;
    const int b = blockIdx.y;
    const int t = threadIdx.x;
    const int N = N_FIXED;

    __shared__ float4 sh[N_FIXED];   // unit vectors

    const float pix = pos[(b * N + i) * 3 + 0];
    const float piy = pos[(b * N + i) * 3 + 1];
    const float piz = pos[(b * N + i) * 3 + 2];

    {
        const int j = t;
        const float px = pos[(b * N + j) * 3 + 0];
        const float py = pos[(b * N + j) * 3 + 1];
        const float pz = pos[(b * N + j) * 3 + 2];
        const float d  = dist[((size_t)b * N + i) * N + j];
        const float inv = (d > 0.0f) ? (1.0f / d) : 0.0f;  // zero vec on j==i
        sh[j] = make_float4((px - pix) * inv, (py - piy) * inv, (pz - piz) * inv, 0.0f);
    }
    __syncthreads();

    const int k0 = (t & 31) * 4;   // owns k0..k0+3
    const int jq = t >> 5;         // j phase (warp-uniform)

    const float4 u0 = sh[k0 + 0];
    const float4 u1 = sh[k0 + 1];
    const float4 u2 = sh[k0 + 2];
    const float4 u3 = sh[k0 + 3];

    float* orow = out + (((size_t)b * N + i) * N) * N;

#pragma unroll 4
    for (int j = jq; j < N; j += 4) {
        const float4 uj = sh[j];

        float c0 = uj.x * u0.x; c0 = fmaf(uj.y, u0.y, c0); c0 = fmaf(uj.z, u0.z, c0);
        float c1 = uj.x * u1.x; c1 = fmaf(uj.y, u1.y, c1); c1 = fmaf(uj.z, u1.z, c1);
        float c2 = uj.x * u2.x; c2 = fmaf(uj.y, u2.y, c2); c2 = fmaf(uj.z, u2.z, c2);
        float c3 = uj.x * u3.x; c3 = fmaf(uj.y, u3.y, c3); c3 = fmaf(uj.z, u3.z, c3);

        // y = 1 - |c|, clamped (guards |c|>1 rounding; doubles as NaN-safety)
        const float y0 = fmaxf(1.0f - fabsf(c0), 1e-12f);
        const float y1 = fmaxf(1.0f - fabsf(c1), 1e-12f);
        const float y2 = fmaxf(1.0f - fabsf(c2), 1e-12f);
        const float y3 = fmaxf(1.0f - fabsf(c3), 1e-12f);

        const float s0 = y0 * rsqrtf(y0);   // sqrt(y)
        const float s1 = y1 * rsqrtf(y1);
        const float s2 = y2 * rsqrtf(y2);
        const float s3 = y3 * rsqrtf(y3);

        float q0 = fmaf(y0, 0.0187293f, 0.0180731f);
        float q1 = fmaf(y1, 0.0187293f, 0.0180731f);
        float q2 = fmaf(y2, 0.0187293f, 0.0180731f);
        float q3 = fmaf(y3, 0.0187293f, 0.0180731f);
        q0 = fmaf(q0, y0, 0.1197803f);
        q1 = fmaf(q1, y1, 0.1197803f);
        q2 = fmaf(q2, y2, 0.1197803f);
        q3 = fmaf(q3, y3, 0.1197803f);
        q0 = fmaf(q0, y0, 1.4141461f);
        q1 = fmaf(q1, y1, 1.4141461f);
        q2 = fmaf(q2, y2, 1.4141461f);
        q3 = fmaf(q3, y3, 1.4141461f);

        const float b0 = s0 * q0;
        const float b1 = s1 * q1;
        const float b2 = s2 * q2;
        const float b3 = s3 * q3;

        float4 v;
        v.x = (c0 < 0.0f) ? (PI_F - b0) : b0;
        v.y = (c1 < 0.0f) ? (PI_F - b1) : b1;
        v.z = (c2 < 0.0f) ? (PI_F - b2) : b2;
        v.w = (c3 < 0.0f) ? (PI_F - b3) : b3;

        *reinterpret_cast<float4*>(orow + (size_t)j * N + k0) = v;
    }

    // fixups: land after all main-loop stores (same block wrote every address)
    __syncthreads();

    // row j == i (128 floats, 32 threads x float4)
    if (t < 32)
        *reinterpret_cast<float4*>(orow + (size_t)i * N + 4 * t) =
            make_float4(0.0f, 0.0f, 0.0f, 0.0f);
    // column k == i and diagonal j == k
    orow[(size_t)t * N + i] = 0.0f;
    orow[(size_t)t * N + t] = 0.0f;
}

extern "C" void kernel_launch(void* const* d_in, const int* in_sizes, int n_in,
                              void* d_out, int out_size) {
    const float* pos  = (const float*)d_in[0];   // positions (B, N, 3)
    const float* dist = (const float*)d_in[1];   // dist_matrix (B, N, N)
    float* out = (float*)d_out;                  // (B, N, N, N) fp32

    const int N = (int)(3LL * in_sizes[1] / in_sizes[0]);   // = 128
    const int B = in_sizes[0] / (3 * N);                    // = 8

    dim3 grid(N, B);
    angle_kernel<<<grid, 128>>>(pos, dist, out);
}